// round 1
// baseline (speedup 1.0000x reference)
#include <cuda_runtime.h>
#include <math_constants.h>

#define T_TOK 32768
#define H_DIM 1024
#define V_DIM 32
#define D_DIM 1024

// ---- scratch (static device globals; zero-initialized at module load) ----
__device__ int   g_tok[T_TOK];
__device__ int   g_run_start[T_TOK];
__device__ int   g_run_dest[T_TOK];
__device__ int   g_R;
__device__ int   g_nvalid;
__device__ float g_compact[(size_t)T_TOK * H_DIM];  // rows >= n_valid remain 0 forever

// ============================================================
// K1: per-token argmax over V=32 (first-occurrence tie-break)
// ============================================================
__global__ void k_argmax(const float* __restrict__ logits) {
    int t = blockIdx.x * blockDim.x + threadIdx.x;
    if (t >= T_TOK) return;
    const float4* p = (const float4*)(logits + (size_t)t * V_DIM);
    float best = -CUDART_INF_F;
    int   bi   = 0;
#pragma unroll
    for (int i = 0; i < 8; i++) {
        float4 v = p[i];
        float vals[4] = {v.x, v.y, v.z, v.w};
#pragma unroll
        for (int j = 0; j < 4; j++) {
            if (vals[j] > best) { best = vals[j]; bi = i * 4 + j; }
        }
    }
    g_tok[t] = bi;
}

// ============================================================
// K2: single-block scan over all T tokens.
//   - run starts (change points), run index, valid (tok!=0) index
//   - writes g_run_start[r], g_run_dest[r] (-1 if blank), g_R, g_nvalid
// 1024 threads x 32 tokens each = 32768.
// ============================================================
__global__ void k_scan() {
    __shared__ int sr[1024];
    __shared__ int sv[1024];
    int tid  = threadIdx.x;
    int base = tid * 32;

    int rc = 0, vc = 0;
    int prev = (base == 0) ? -1 : g_tok[base - 1];
#pragma unroll
    for (int i = 0; i < 32; i++) {
        int tk = g_tok[base + i];
        if (tk != prev) { rc++; if (tk != 0) vc++; }
        prev = tk;
    }
    sr[tid] = rc; sv[tid] = vc;
    __syncthreads();

    // inclusive Hillis-Steele scan over 1024 per-thread totals
    for (int off = 1; off < 1024; off <<= 1) {
        int r = sr[tid], v = sv[tid];
        int ra = 0, va = 0;
        if (tid >= off) { ra = sr[tid - off]; va = sv[tid - off]; }
        __syncthreads();
        sr[tid] = r + ra; sv[tid] = v + va;
        __syncthreads();
    }

    int rbase = sr[tid] - rc;   // exclusive offsets for this thread's chunk
    int vbase = sv[tid] - vc;
    if (tid == 1023) { g_R = sr[1023]; g_nvalid = sv[1023]; }

    // second pass: emit run records
    prev = (base == 0) ? -1 : g_tok[base - 1];
#pragma unroll
    for (int i = 0; i < 32; i++) {
        int tk = g_tok[base + i];
        if (tk != prev) {
            g_run_start[rbase] = base + i;
            g_run_dest[rbase]  = (tk != 0) ? vbase : -1;
            if (tk != 0) vbase++;
            rbase++;
        }
        prev = tk;
    }
}

// ============================================================
// K3: per-run mean of hidden rows -> g_compact[dest]
// one block per run candidate; 256 threads x float4 covers H=1024
// ============================================================
__global__ void k_means(const float* __restrict__ hidden) {
    int r = blockIdx.x;
    if (r >= g_R) return;
    int d = g_run_dest[r];
    if (d < 0) return;
    int s = g_run_start[r];
    int e = (r + 1 < g_R) ? g_run_start[r + 1] : T_TOK;
    float inv = 1.0f / (float)(e - s);

    int c = threadIdx.x;  // 0..255, one float4 each
    float4 acc = make_float4(0.f, 0.f, 0.f, 0.f);
    for (int row = s; row < e; row++) {
        float4 v = ((const float4*)(hidden + (size_t)row * H_DIM))[c];
        acc.x += v.x; acc.y += v.y; acc.z += v.z; acc.w += v.w;
    }
    acc.x *= inv; acc.y *= inv; acc.z *= inv; acc.w *= inv;
    ((float4*)(g_compact + (size_t)d * H_DIM))[c] = acc;
}

// ============================================================
// K4: SGEMM  out[t, n] = mask(t) * (sum_k compact[t,k] * W[n,k] + b[n])
// 128x128x8 tiles, 256 threads, 8x8 register tiles.
// ============================================================
#define BM 128
#define BN 128
#define BK 8
#define TM 8
#define TN 8

__global__ void __launch_bounds__(256, 2)
k_gemm(const float* __restrict__ W, const float* __restrict__ b,
       float* __restrict__ out) {
    __shared__ float As[BK][BM];
    __shared__ float Bs[BK][BN];

    int bn = blockIdx.x;       // 0..7   (fast dim -> A-tile L2 reuse)
    int bm = blockIdx.y;       // 0..255
    int tid = threadIdx.x;
    int tx = tid & 15;         // 0..15
    int ty = tid >> 4;         // 0..15
    int row0 = bm * BM;
    int col0 = bn * BN;

    // global-load mapping: 256 float4 loads cover a 128x8 tile
    int lr = tid >> 1;           // 0..127
    int lk = (tid & 1) * 4;      // 0 or 4
    const float* Aptr = g_compact + (size_t)(row0 + lr) * H_DIM + lk;
    const float* Bptr = W        + (size_t)(col0 + lr) * H_DIM + lk;

    float acc[TM][TN];
#pragma unroll
    for (int i = 0; i < TM; i++)
#pragma unroll
        for (int j = 0; j < TN; j++) acc[i][j] = 0.f;

    for (int kb = 0; kb < H_DIM; kb += BK) {
        float4 a = *(const float4*)(Aptr + kb);
        float4 w = *(const float4*)(Bptr + kb);
        As[lk + 0][lr] = a.x; As[lk + 1][lr] = a.y;
        As[lk + 2][lr] = a.z; As[lk + 3][lr] = a.w;
        Bs[lk + 0][lr] = w.x; Bs[lk + 1][lr] = w.y;
        Bs[lk + 2][lr] = w.z; Bs[lk + 3][lr] = w.w;
        __syncthreads();

#pragma unroll
        for (int k = 0; k < BK; k++) {
            float4 a0 = *(const float4*)&As[k][ty * TM];
            float4 a1 = *(const float4*)&As[k][ty * TM + 4];
            float4 b0 = *(const float4*)&Bs[k][tx * TN];
            float4 b1 = *(const float4*)&Bs[k][tx * TN + 4];
            float ar[TM] = {a0.x, a0.y, a0.z, a0.w, a1.x, a1.y, a1.z, a1.w};
            float br[TN] = {b0.x, b0.y, b0.z, b0.w, b1.x, b1.y, b1.z, b1.w};
#pragma unroll
            for (int i = 0; i < TM; i++)
#pragma unroll
                for (int j = 0; j < TN; j++)
                    acc[i][j] = fmaf(ar[i], br[j], acc[i][j]);
        }
        __syncthreads();
    }

    int nvalid = g_nvalid;
#pragma unroll
    for (int i = 0; i < TM; i++) {
        int row = row0 + ty * TM + i;
        bool m = (row < nvalid);
#pragma unroll
        for (int j = 0; j < TN; j += 4) {
            int col = col0 + tx * TN + j;
            float4 o;
            o.x = m ? (acc[i][j + 0] + b[col + 0]) : 0.f;
            o.y = m ? (acc[i][j + 1] + b[col + 1]) : 0.f;
            o.z = m ? (acc[i][j + 2] + b[col + 2]) : 0.f;
            o.w = m ? (acc[i][j + 3] + b[col + 3]) : 0.f;
            *(float4*)(out + (size_t)row * D_DIM + col) = o;
        }
    }
}

// ============================================================
extern "C" void kernel_launch(void* const* d_in, const int* in_sizes, int n_in,
                              void* d_out, int out_size) {
    const float* hidden = (const float*)d_in[0];  // [1, T, H]
    const float* logits = (const float*)d_in[1];  // [1, T, V]
    const float* W      = (const float*)d_in[2];  // [D, H]
    const float* b      = (const float*)d_in[3];  // [D]
    float* out = (float*)d_out;                   // [1, T, D]

    k_argmax<<<T_TOK / 256, 256>>>(logits);
    k_scan<<<1, 1024>>>();
    k_means<<<T_TOK, 256>>>(hidden);
    dim3 grid(D_DIM / BN, T_TOK / BM);
    k_gemm<<<grid, 256>>>(W, b, out);
}

// round 3
// speedup vs baseline: 3.0888x; 3.0888x over previous
#include <cuda_runtime.h>
#include <cuda_bf16.h>
#include <math_constants.h>
#include <cstdint>

#define T_TOK 32768
#define H_DIM 1024
#define V_DIM 32
#define D_DIM 1024
#define KEXP  2048          // [hi | lo] storage width

// ---- scratch (static device globals; zero-initialized at module load) ----
__device__ int   g_tok[T_TOK];
__device__ int   g_run_start[T_TOK];
__device__ int   g_run_dest[T_TOK];
__device__ int   g_R;
__device__ int   g_nvalid;
__device__ __nv_bfloat16 g_A[(size_t)T_TOK * KEXP];   // rows >= n_valid stay 0
__device__ __nv_bfloat16 g_W[(size_t)D_DIM * KEXP];

// ============================================================
// helpers
// ============================================================
__device__ __forceinline__ uint32_t smem_u32(const void* p) {
    return (uint32_t)__cvta_generic_to_shared(p);
}
__device__ __forceinline__ void cp16(uint32_t dst, const void* src) {
    asm volatile("cp.async.cg.shared.global [%0], [%1], 16;\n" :: "r"(dst), "l"(src));
}
__device__ __forceinline__ void ldmx4(uint32_t* r, uint32_t a) {
    asm volatile("ldmatrix.sync.aligned.m8n8.x4.shared.b16 {%0,%1,%2,%3}, [%4];"
                 : "=r"(r[0]), "=r"(r[1]), "=r"(r[2]), "=r"(r[3]) : "r"(a));
}
__device__ __forceinline__ void mma16816(float* c, const uint32_t* a, const uint32_t* b) {
    asm volatile(
        "mma.sync.aligned.m16n8k16.row.col.f32.bf16.bf16.f32 "
        "{%0,%1,%2,%3},{%4,%5,%6,%7},{%8,%9},{%0,%1,%2,%3};"
        : "+f"(c[0]), "+f"(c[1]), "+f"(c[2]), "+f"(c[3])
        : "r"(a[0]), "r"(a[1]), "r"(a[2]), "r"(a[3]), "r"(b[0]), "r"(b[1]));
}
#define SW128(o) ((o) ^ (((o) >> 3) & 0x70))

// ============================================================
// K1: argmax over V=32 (first-occurrence tie-break)
// ============================================================
__global__ void k_argmax(const float* __restrict__ logits) {
    int t = blockIdx.x * blockDim.x + threadIdx.x;
    if (t >= T_TOK) return;
    const float4* p = (const float4*)(logits + (size_t)t * V_DIM);
    float best = -CUDART_INF_F;
    int bi = 0;
#pragma unroll
    for (int i = 0; i < 8; i++) {
        float4 v = p[i];
        float vals[4] = {v.x, v.y, v.z, v.w};
#pragma unroll
        for (int j = 0; j < 4; j++)
            if (vals[j] > best) { best = vals[j]; bi = i * 4 + j; }
    }
    g_tok[t] = bi;
}

// ============================================================
// K2: single-block run-length scan (1024 thr x 32 tokens)
// ============================================================
__global__ void k_scan() {
    __shared__ int sr[1024];
    __shared__ int sv[1024];
    int tid = threadIdx.x;
    int base = tid * 32;

    int rc = 0, vc = 0;
    int prev = (base == 0) ? -1 : g_tok[base - 1];
#pragma unroll
    for (int i = 0; i < 32; i++) {
        int tk = g_tok[base + i];
        if (tk != prev) { rc++; if (tk != 0) vc++; }
        prev = tk;
    }
    sr[tid] = rc; sv[tid] = vc;
    __syncthreads();
    for (int off = 1; off < 1024; off <<= 1) {
        int r = sr[tid], v = sv[tid];
        int ra = 0, va = 0;
        if (tid >= off) { ra = sr[tid - off]; va = sv[tid - off]; }
        __syncthreads();
        sr[tid] = r + ra; sv[tid] = v + va;
        __syncthreads();
    }
    int rbase = sr[tid] - rc;
    int vbase = sv[tid] - vc;
    if (tid == 1023) { g_R = sr[1023]; g_nvalid = sv[1023]; }

    prev = (base == 0) ? -1 : g_tok[base - 1];
#pragma unroll
    for (int i = 0; i < 32; i++) {
        int tk = g_tok[base + i];
        if (tk != prev) {
            g_run_start[rbase] = base + i;
            g_run_dest[rbase] = (tk != 0) ? vbase : -1;
            if (tk != 0) vbase++;
            rbase++;
        }
        prev = tk;
    }
}

// ============================================================
// K3: per-run mean -> split bf16 (hi | lo) rows of g_A
// ============================================================
__global__ void k_means(const float* __restrict__ hidden) {
    int r = blockIdx.x;
    if (r >= g_R) return;
    int d = g_run_dest[r];
    if (d < 0) return;
    int s = g_run_start[r];
    int e = (r + 1 < g_R) ? g_run_start[r + 1] : T_TOK;
    float inv = 1.0f / (float)(e - s);

    int c = threadIdx.x;  // 0..255, 4 floats each
    float4 acc = make_float4(0.f, 0.f, 0.f, 0.f);
    for (int row = s; row < e; row++) {
        float4 v = ((const float4*)(hidden + (size_t)row * H_DIM))[c];
        acc.x += v.x; acc.y += v.y; acc.z += v.z; acc.w += v.w;
    }
    float m[4] = {acc.x * inv, acc.y * inv, acc.z * inv, acc.w * inv};
    __nv_bfloat16 hi[4], lo[4];
#pragma unroll
    for (int j = 0; j < 4; j++) {
        hi[j] = __float2bfloat16(m[j]);
        lo[j] = __float2bfloat16(m[j] - __bfloat162float(hi[j]));
    }
    size_t base = (size_t)d * KEXP + c * 4;
    *(uint2*)(g_A + base)        = *(uint2*)hi;
    *(uint2*)(g_A + base + 1024) = *(uint2*)lo;
}

// ============================================================
// K4: split W (fp32 -> bf16 hi | lo)
// ============================================================
__global__ void k_wsplit(const float* __restrict__ W) {
    int i = blockIdx.x * 256 + threadIdx.x;   // 0 .. 1M-1
    float v = W[i];
    __nv_bfloat16 hi = __float2bfloat16(v);
    __nv_bfloat16 lo = __float2bfloat16(v - __bfloat162float(hi));
    int r = i >> 10, c = i & 1023;
    g_W[(size_t)r * KEXP + c]        = hi;
    g_W[(size_t)r * KEXP + 1024 + c] = lo;
}

// ============================================================
// K5: mma.sync bf16 GEMM, 128x128 CTA tile, BK=64, 3 cp.async stages
//     K_eff = 3072 (3-term split: A_hi*W_hi + A_hi*W_lo + A_lo*W_hi)
// ============================================================
#define BM 128
#define BN 128
#define KTILES 48
#define STAGE_BYTES 32768     // A 16KB + B 16KB
#define OFF_B 16384
#define SMEM_REQ (3 * STAGE_BYTES)

__device__ __forceinline__ void load_stage(uint32_t sb, int kt, int row0, int col0, int tid) {
    int s = kt % 3;
    int p = kt >> 4, q = kt & 15;
    int aCol = (p == 2 ? 1024 : 0) + q * 64;   // phase2 uses A_lo
    int wCol = (p == 1 ? 1024 : 0) + q * 64;   // phase1 uses W_lo
    uint32_t sA = sb + s * STAGE_BYTES;
    uint32_t sB = sA + OFF_B;
    const __nv_bfloat16* Abase = g_A + (size_t)row0 * KEXP + aCol;
    const __nv_bfloat16* Wbase = g_W + (size_t)col0 * KEXP + wCol;
#pragma unroll
    for (int i = 0; i < 4; i++) {               // A: 128 rows x 128B = 1024 chunks
        int c = i * 256 + tid;
        int r = c >> 3, k = c & 7;
        cp16(sA + SW128(r * 128 + k * 16), Abase + (size_t)r * KEXP + k * 8);
    }
#pragma unroll
    for (int i = 0; i < 4; i++) {               // B: 128 rows x 128B
        int c = i * 256 + tid;
        int r = c >> 3, k = c & 7;
        cp16(sB + SW128(r * 128 + k * 16), Wbase + (size_t)r * KEXP + k * 8);
    }
    asm volatile("cp.async.commit_group;\n" ::: "memory");
}

__global__ void __launch_bounds__(256, 2)
k_gemm_mma(const float* __restrict__ bias, float* __restrict__ out) {
    extern __shared__ char smem_raw[];
    uint32_t sb = smem_u32(smem_raw);
    const int tid = threadIdx.x;
    const int lane = tid & 31;
    const int wid = tid >> 5;
    const int row0 = blockIdx.y * BM;
    const int col0 = blockIdx.x * BN;
    const int wm = (wid & 1) * 64;     // warp M offset within tile
    const int wn = (wid >> 1) * 32;    // warp N offset within tile

    // ldmatrix per-lane address components
    const int aRow = (lane & 7) + ((lane >> 3) & 1) * 8;  // + mt*16 + wm
    const int aColB = (lane >> 4) * 16;                   // byte offset within k16
    const int bRow = (lane & 7) + (lane >> 4) * 8;        // + nt2*16 + wn
    const int bColB = ((lane >> 3) & 1) * 16;

    float acc[4][4][4];
#pragma unroll
    for (int i = 0; i < 4; i++)
#pragma unroll
        for (int j = 0; j < 4; j++)
#pragma unroll
            for (int k = 0; k < 4; k++) acc[i][j][k] = 0.f;

    load_stage(sb, 0, row0, col0, tid);
    load_stage(sb, 1, row0, col0, tid);

    for (int kt = 0; kt < KTILES; kt++) {
        if (kt == KTILES - 1) asm volatile("cp.async.wait_group 0;\n" ::: "memory");
        else                  asm volatile("cp.async.wait_group 1;\n" ::: "memory");
        __syncthreads();

        if (kt + 2 < KTILES) load_stage(sb, kt + 2, row0, col0, tid);

        uint32_t sA = sb + (kt % 3) * STAGE_BYTES;
        uint32_t sBt = sA + OFF_B;
#pragma unroll
        for (int kk = 0; kk < 4; kk++) {        // 4 x k16 per BK=64
            uint32_t a[4][4];
#pragma unroll
            for (int mt = 0; mt < 4; mt++)
                ldmx4(a[mt], sA + SW128((wm + mt * 16 + aRow) * 128 + kk * 32 + aColB));
            uint32_t b[2][4];
#pragma unroll
            for (int nt2 = 0; nt2 < 2; nt2++)
                ldmx4(b[nt2], sBt + SW128((wn + nt2 * 16 + bRow) * 128 + kk * 32 + bColB));
#pragma unroll
            for (int mt = 0; mt < 4; mt++)
#pragma unroll
                for (int nt = 0; nt < 4; nt++)
                    mma16816(acc[mt][nt], a[mt], &b[nt >> 1][(nt & 1) * 2]);
        }
        __syncthreads();
    }

    // epilogue: +bias, mask rows >= n_valid, write fp32
    int nv = g_nvalid;
#pragma unroll
    for (int mt = 0; mt < 4; mt++) {
        int rbase = row0 + wm + mt * 16 + (lane >> 2);
#pragma unroll
        for (int h = 0; h < 2; h++) {
            int row = rbase + h * 8;
            bool valid = row < nv;
            float* orow = out + (size_t)row * D_DIM;
#pragma unroll
            for (int nt = 0; nt < 4; nt++) {
                int col = col0 + wn + nt * 8 + (lane & 3) * 2;
                float2 o;
                o.x = valid ? (acc[mt][nt][h * 2 + 0] + bias[col + 0]) : 0.f;
                o.y = valid ? (acc[mt][nt][h * 2 + 1] + bias[col + 1]) : 0.f;
                *(float2*)(orow + col) = o;
            }
        }
    }
}

// ============================================================
extern "C" void kernel_launch(void* const* d_in, const int* in_sizes, int n_in,
                              void* d_out, int out_size) {
    const float* hidden = (const float*)d_in[0];  // [1, T, H]
    const float* logits = (const float*)d_in[1];  // [1, T, V]
    const float* W      = (const float*)d_in[2];  // [D, H]
    const float* b      = (const float*)d_in[3];  // [D]
    float* out = (float*)d_out;                   // [1, T, D]

    cudaFuncSetAttribute(k_gemm_mma, cudaFuncAttributeMaxDynamicSharedMemorySize, SMEM_REQ);

    k_argmax<<<T_TOK / 256, 256>>>(logits);
    k_scan<<<1, 1024>>>();
    k_means<<<T_TOK, 256>>>(hidden);
    k_wsplit<<<(D_DIM * H_DIM) / 256, 256>>>(W);
    dim3 grid(D_DIM / BN, T_TOK / BM);
    k_gemm_mma<<<grid, 256, SMEM_REQ>>>(b, out);
}